// round 7
// baseline (speedup 1.0000x reference)
#include <cuda_runtime.h>
#include <cuda_fp16.h>
#include <cstdint>

// ---------------- constants ----------------
#define NVAR   64
#define HID1   256
#define HID2   128
#define BATCH  16384
#define BT     64                  // batch rows per CTA
#define NCTA   (BATCH / BT)        // 256 CTAs -> 2 per SM
#define NCHUNK 256                 // 64 vars x 4 quarters
#define KTMAX  5
#define W2H    8192                // halfs per W2 chunk
#define AS     88                  // Ac row stride (halfs) - ldmatrix conflict-free
#define HS     72                  // sH row stride (halfs) - ldmatrix conflict-free
#define YCS    64                  // Yc column stride (halfs per var column)

// SMEM byte offsets
#define OFF_AC 0                          // 64 x 88 halfs  = 11264
#define OFF_YC 11264                      // 64 x 64 halfs  =  8192
#define OFF_H  19456                      // 64 x 72 halfs  =  9216
#define OFF_W1 28672                      // 2 x 10240      = 20480
#define OFF_W2 49152                      // 2 x 16384      = 32768
#define OFF_B1 81920                      // 2 x 256 f      =  2048
#define OFF_B2 83968                      // 2 x 128 f      =  1024
#define OFF_W3 84992                      // 2 x 128 f      =  1024
#define OFF_B3 86016                      // 2 f (+pad)     =    16
#define OFF_SP 86032                      // 4 x 64 f       =  1024
#define SMEM_TOTAL 87056                  // x2 CTAs = 174KB <= 227KB

// ---------------- device scratch (no allocs allowed) ----------------
__device__ __half g_W1h[NVAR * 4 * KTMAX * 1024];  // packed variable-length chunks
__device__ __half g_W2h[NCHUNK * W2H];
__device__ __half g_Uth[NVAR * BATCH];
__device__ int    g_plist[NVAR * NVAR];
__device__ int    g_pcnt[NVAR];
__device__ int    g_KT[NVAR];
__device__ int    g_off1[NVAR];            // halfs offset of var's W1 chunks

// ---------------- helpers ----------------
static __device__ __forceinline__ void mma16(float* c, const unsigned* a,
                                             unsigned b0, unsigned b1) {
    asm volatile(
        "mma.sync.aligned.m16n8k16.row.col.f32.f16.f16.f32 "
        "{%0,%1,%2,%3},{%4,%5,%6,%7},{%8,%9},{%0,%1,%2,%3};\n"
        : "+f"(c[0]), "+f"(c[1]), "+f"(c[2]), "+f"(c[3])
        : "r"(a[0]), "r"(a[1]), "r"(a[2]), "r"(a[3]), "r"(b0), "r"(b1));
}

static __device__ __forceinline__ void ldmA(unsigned* a, uint32_t saddr) {
    asm volatile("ldmatrix.sync.aligned.m8n8.x4.shared.b16 {%0,%1,%2,%3}, [%4];"
        : "=r"(a[0]), "=r"(a[1]), "=r"(a[2]), "=r"(a[3]) : "r"(saddr));
}

static __device__ __forceinline__ void cp16(void* sdst, const void* gsrc) {
    unsigned sa = (unsigned)__cvta_generic_to_shared(sdst);
    asm volatile("cp.async.cg.shared.global [%0], [%1], 16;\n" :: "r"(sa), "l"(gsrc));
}

#define CP_COMMIT() asm volatile("cp.async.commit_group;\n" ::: "memory")
#define CP_WAIT1()  asm volatile("cp.async.wait_group 1;\n" ::: "memory")

// ---------------- prep kernels ----------------
// parent lists, KT (k-tiles incl. u), prefix offsets. One block, 64 threads.
__global__ void sen_prep_meta(const int* __restrict__ G) {
    int i = threadIdx.x;
    int np = 0;
    for (int j = 0; j < i; ++j)
        if (G[j * NVAR + i] > 0) g_plist[i * NVAR + np++] = j;
    g_pcnt[i] = np;
    g_KT[i] = (np + 16) / 16;          // ceil((np+1)/16)
    __syncthreads();
    if (i == 0) {
        int off = 0;
        for (int v = 0; v < NVAR; ++v) { g_off1[v] = off; off += 4 * g_KT[v] * 1024; }
    }
}

// W1 packed frag-major fp16, compact K (parents then u then zero-pad).
// chunk(i,q): [n4=4][kt=ktc][lane=32][8 halfs]; h: n8l=h>>2, p=(h>>1)&1, e=h&1
//   k = kt*16 + (lane&3)*2 + 8p + e ; n = q*64 + n4*16 + n8l*8 + (lane>>2)
__global__ void sen_prep_w1h(const float* __restrict__ W1) {
    int idx = blockIdx.x * blockDim.x + threadIdx.x;
    if (idx >= NVAR * 4 * KTMAX * 1024) return;
    int i    = idx / (4 * KTMAX * 1024);
    int rem  = idx % (4 * KTMAX * 1024);
    int q    = rem / (KTMAX * 1024);
    int rem2 = rem % (KTMAX * 1024);
    int n4   = rem2 / (KTMAX * 256);
    int rem3 = rem2 % (KTMAX * 256);
    int kt   = rem3 / 256;
    int f    = rem3 % 256;
    int lane = f >> 3, h = f & 7;
    int ktc = g_KT[i];
    if (kt >= ktc) return;
    int n8l = h >> 2, p = (h >> 1) & 1, e = h & 1;
    int k = kt * 16 + (lane & 3) * 2 + 8 * p + e;
    int n = q * 64 + n4 * 16 + n8l * 8 + (lane >> 2);
    int np = g_pcnt[i];
    float val = 0.f;
    if (k < np)       val = W1[(i * (NVAR + 1) + g_plist[i * NVAR + k]) * HID1 + n];
    else if (k == np) val = W1[(i * (NVAR + 1) + NVAR) * HID1 + n];
    int dst = g_off1[i] + q * ktc * 1024 + ((n4 * ktc + kt) * 32 + lane) * 8 + h;
    g_W1h[dst] = __float2half_rn(val);
}

// W2 frag-major fp16: chunk t: [n4=4][kt=4][lane=32][16 halfs]
//   k = q*64 + kt*16 + (lane&3)*2 + 8p + e ; n = n4*32 + n8l*8 + (lane>>2)
__global__ void sen_prep_w2h(const float* __restrict__ W2) {
    int idx = blockIdx.x * blockDim.x + threadIdx.x;
    if (idx >= NCHUNK * W2H) return;
    int t    = idx / W2H;
    int rem  = idx % W2H;
    int n4   = rem / 2048;
    int rem2 = rem % 2048;
    int kt   = rem2 / 512;
    int f    = rem2 % 512;
    int lane = f >> 4, h = f & 15;
    int n8l = h >> 2, p = (h >> 1) & 1, e = h & 1;
    int i = t >> 2, q = t & 3;
    int k = q * 64 + kt * 16 + (lane & 3) * 2 + 8 * p + e;
    int n = n4 * 32 + n8l * 8 + (lane >> 2);
    int dst = t * W2H + ((n4 * 4 + kt) * 32 + lane) * 16 + h;
    g_W2h[dst] = __float2half_rn(W2[(i * HID1 + k) * HID2 + n]);
}

__global__ void sen_prep_ut(const float* __restrict__ U) {
    int idx = blockIdx.x * blockDim.x + threadIdx.x;
    if (idx >= NVAR * BATCH) return;
    int v = idx / BATCH;
    int b = idx - v * BATCH;
    g_Uth[idx] = __float2half_rn(U[b * NVAR + v]);
}

// ---------------- main kernel: 256 threads, 2 CTAs/SM ----------------
__global__ void __launch_bounds__(256, 2) sen_main(
    const float* __restrict__ X,
    const float* __restrict__ b1g,
    const float* __restrict__ b2g,
    const float* __restrict__ W3g,
    const float* __restrict__ b3g,
    float* __restrict__ out)
{
    extern __shared__ char smem[];
    __half* Ac  = (__half*)(smem + OFF_AC);
    __half* Yc  = (__half*)(smem + OFF_YC);
    __half* sH  = (__half*)(smem + OFF_H);
    float*  sB1 = (float*)(smem + OFF_B1);
    float*  sB2 = (float*)(smem + OFF_B2);
    float*  sW3 = (float*)(smem + OFF_W3);
    float*  sB3 = (float*)(smem + OFF_B3);
    float*  sP  = (float*)(smem + OFF_SP);
    const uint32_t smb = (uint32_t)__cvta_generic_to_shared(smem);

    const int tid  = threadIdx.x;
    const int lane = tid & 31;
    const int w    = tid >> 5;
    const int wm   = w >> 2;                // M group 0..1 (rows 32*wm..+32)
    const int gnI  = w & 3;                 // N group 0..3
    const int b0   = blockIdx.x * BT;
    const int r0   = 32 * wm + (lane >> 2);
    const int ccol = (lane & 3) * 2;

    const uint32_t aAb = smb + OFF_AC +
        ((((32 * wm + (lane & 15)) * AS) + (lane >> 4) * 8) << 1);
    const uint32_t aHb = smb + OFF_H +
        ((((32 * wm + (lane & 15)) * HS) + (lane >> 4) * 8) << 1);

    // init Yc (column-major) from X
    for (int idx = tid; idx < NVAR * BT; idx += 256) {
        int v = idx >> 6, r = idx & 63;
        Yc[v * YCS + r] = __float2half_rn(X[(size_t)(b0 + r) * NVAR + v]);
    }
    // var-0 biases (parity 0)
    sB1[tid] = __ldg(b1g + tid);
    if (tid < 128) { sB2[tid] = __ldg(b2g + tid); sW3[tid] = __ldg(W3g + tid); }
    if (tid == 0) sB3[0] = __ldg(b3g);

    // prologue: prefetch chunk 0 (W1 var0 q0 + W2 chunk0)
    {
        int kt0 = __ldg(g_KT);
        const char* s1 = (const char*)g_W1h;     // off1[0] = 0
        char* d1 = smem + OFF_W1;
        for (int idx = tid; idx < kt0 * 128; idx += 256) cp16(d1 + idx * 16, s1 + idx * 16);
        const char* s2 = (const char*)g_W2h;
        char* d2 = smem + OFF_W2;
        for (int idx = tid; idx < 1024; idx += 256) cp16(d2 + idx * 16, s2 + idx * 16);
        CP_COMMIT();
    }

    float acc2[2][4][4];
    #pragma unroll
    for (int m = 0; m < 2; ++m)
        #pragma unroll
        for (int n = 0; n < 4; ++n)
            #pragma unroll
            for (int e = 0; e < 4; ++e) acc2[m][n][e] = 0.f;

    #pragma unroll 1
    for (int i = 0; i < NVAR; ++i) {
        const int pb  = i & 1;
        const int np  = __ldg(g_pcnt + i);
        const int ktc = __ldg(g_KT + i);
        const int off = __ldg(g_off1 + i);
        const int kc  = ktc * 16;

        __syncthreads();   // Yc(i-1) written; Ac free (prev var's L1 done)

        // gather compact A tile: cols [0..np) parents, np = u, rest 0
        for (int idx = tid; idx < (kc << 6); idx += 256) {
            int c = idx >> 6, r = idx & 63;
            __half v;
            if (c < np)       v = Yc[__ldg(g_plist + i * NVAR + c) * YCS + r];
            else if (c == np) v = g_Uth[(size_t)i * BATCH + b0 + r];
            else              v = __half(0.f);
            Ac[r * AS + c] = v;
        }

        #pragma unroll 1
        for (int q = 0; q < 4; ++q) {
            const int t = i * 4 + q;
            __syncthreads();   // sH consumed; W1 buf (t+1)&1 free; Ac gathered (q==0)

            // prefetch chunk t+1
            if (t + 1 < NCHUNK) {
                int ktc2, off2, q2;
                if (q < 3) { ktc2 = ktc; off2 = off; q2 = q + 1; }
                else       { ktc2 = __ldg(g_KT + i + 1); off2 = __ldg(g_off1 + i + 1); q2 = 0; }
                const char* s1 = (const char*)(g_W1h + off2 + q2 * ktc2 * 1024);
                char* d1 = smem + OFF_W1 + ((t + 1) & 1) * 10240;
                for (int idx = tid; idx < ktc2 * 128; idx += 256)
                    cp16(d1 + idx * 16, s1 + idx * 16);
                const char* s2 = (const char*)(g_W2h + (size_t)(t + 1) * W2H);
                char* d2 = smem + OFF_W2 + ((t + 1) & 1) * 16384;
                for (int idx = tid; idx < 1024; idx += 256)
                    cp16(d2 + idx * 16, s2 + idx * 16);
            }
            CP_COMMIT();
            // stage next var's biases (spread across q0/q1)
            if (q == 0 && i + 1 < NVAR)
                sB1[((i + 1) & 1) * 256 + tid] = __ldg(b1g + (i + 1) * HID1 + tid);
            if (q == 1 && i + 1 < NVAR) {
                const int nb = (i + 1) & 1;
                if (tid < 128) {
                    sB2[nb * 128 + tid] = __ldg(b2g + (i + 1) * HID2 + tid);
                    sW3[nb * 128 + tid] = __ldg(W3g + (i + 1) * HID2 + tid);
                }
                if (tid == 0) sB3[nb] = __ldg(b3g + i + 1);
            }
            CP_WAIT1();        // chunk t landed
            __syncthreads();

            // ---- L1: 64M x 64N x (ktc*16)K, warp tile 32M x 16N ----
            float c1[2][2][4];
            #pragma unroll
            for (int m = 0; m < 2; ++m)
                #pragma unroll
                for (int n = 0; n < 2; ++n)
                    #pragma unroll
                    for (int e = 0; e < 4; ++e) c1[m][n][e] = 0.f;

            const char* wb1 = smem + OFF_W1 + (t & 1) * 10240;
            #pragma unroll 1
            for (int kt = 0; kt < ktc; ++kt) {
                unsigned a0[4], a1[4];
                ldmA(a0, aAb + kt * 32);
                ldmA(a1, aAb + kt * 32 + 16 * AS * 2);
                uint4 bb = *(const uint4*)(wb1 + (((gnI * ktc + kt) * 32 + lane) << 4));
                mma16(c1[0][0], a0, bb.x, bb.y);
                mma16(c1[0][1], a0, bb.z, bb.w);
                mma16(c1[1][0], a1, bb.x, bb.y);
                mma16(c1[1][1], a1, bb.z, bb.w);
            }

            // ---- epilogue: +b1, relu, fp16 -> sH (cols gnI*16..+16) ----
            {
                const float* B1 = sB1 + pb * 256 + q * 64;
                #pragma unroll
                for (int Mt = 0; Mt < 2; ++Mt) {
                    const int rA = r0 + 16 * Mt;
                    #pragma unroll
                    for (int n8 = 0; n8 < 2; ++n8) {
                        const int c = gnI * 16 + n8 * 8 + ccol;
                        const float bi0 = B1[c], bi1 = B1[c + 1];
                        __half2 hA = __floats2half2_rn(
                            fmaxf(c1[Mt][n8][0] + bi0, 0.f),
                            fmaxf(c1[Mt][n8][1] + bi1, 0.f));
                        __half2 hB = __floats2half2_rn(
                            fmaxf(c1[Mt][n8][2] + bi0, 0.f),
                            fmaxf(c1[Mt][n8][3] + bi1, 0.f));
                        *(__half2*)(sH + rA * HS + c)       = hA;
                        *(__half2*)(sH + (rA + 8) * HS + c) = hB;
                    }
                }
            }
            __syncthreads();

            // ---- L2 partial: 64M x 128N x 64K, warp tile 32M x 32N ----
            const char* wb2 = smem + OFF_W2 + (t & 1) * 16384;
            #pragma unroll
            for (int kt = 0; kt < 4; ++kt) {
                unsigned a0[4], a1[4];
                ldmA(a0, aHb + kt * 32);
                ldmA(a1, aHb + kt * 32 + 16 * HS * 2);
                const char* bp = wb2 + (((gnI * 4 + kt) * 32 + lane) << 5);
                uint4 bA = *(const uint4*)(bp);
                uint4 bB = *(const uint4*)(bp + 16);
                mma16(acc2[0][0], a0, bA.x, bA.y);
                mma16(acc2[0][1], a0, bA.z, bA.w);
                mma16(acc2[0][2], a0, bB.x, bB.y);
                mma16(acc2[0][3], a0, bB.z, bB.w);
                mma16(acc2[1][0], a1, bA.x, bA.y);
                mma16(acc2[1][1], a1, bA.z, bA.w);
                mma16(acc2[1][2], a1, bB.x, bB.y);
                mma16(acc2[1][3], a1, bB.z, bB.w);
            }
        } // q

        // ---- L3: y = relu(acc2 + b2) . w3 + b3 ----
        {
            const float* B2  = sB2 + pb * 128;
            const float* W3s = sW3 + pb * 128;
            float yv[2][2];
            #pragma unroll
            for (int Mt = 0; Mt < 2; ++Mt) {
                float pA = 0.f, pB = 0.f;
                #pragma unroll
                for (int nt = 0; nt < 4; ++nt) {
                    const int c = gnI * 32 + nt * 8 + ccol;
                    const float w30 = W3s[c], w31 = W3s[c + 1];
                    const float d0 = B2[c], d1 = B2[c + 1];
                    pA = fmaf(fmaxf(acc2[Mt][nt][0] + d0, 0.f), w30, pA);
                    pA = fmaf(fmaxf(acc2[Mt][nt][1] + d1, 0.f), w31, pA);
                    pB = fmaf(fmaxf(acc2[Mt][nt][2] + d0, 0.f), w30, pB);
                    pB = fmaf(fmaxf(acc2[Mt][nt][3] + d1, 0.f), w31, pB);
                    acc2[Mt][nt][0] = 0.f; acc2[Mt][nt][1] = 0.f;
                    acc2[Mt][nt][2] = 0.f; acc2[Mt][nt][3] = 0.f;
                }
                pA += __shfl_xor_sync(0xffffffffu, pA, 1);
                pA += __shfl_xor_sync(0xffffffffu, pA, 2);
                pB += __shfl_xor_sync(0xffffffffu, pB, 1);
                pB += __shfl_xor_sync(0xffffffffu, pB, 2);
                yv[Mt][0] = pA; yv[Mt][1] = pB;
            }
            if ((lane & 3) == 0) {
                sP[gnI * 64 + r0]      = yv[0][0];
                sP[gnI * 64 + r0 + 8]  = yv[0][1];
                sP[gnI * 64 + r0 + 16] = yv[1][0];
                sP[gnI * 64 + r0 + 24] = yv[1][1];
            }
            __syncthreads();
            if (gnI == 0 && (lane & 3) == 0) {
                const float b3v = sB3[pb];
                #pragma unroll
                for (int s = 0; s < 4; ++s) {
                    const int r = r0 + 8 * s;
                    const float y = sP[r] + sP[64 + r] + sP[128 + r] + sP[192 + r] + b3v;
                    Yc[i * YCS + r] = __float2half_rn(y);      // fp16 for later vars
                    out[(size_t)(b0 + r) * NVAR + i] = y;      // fp32 output direct
                }
            }
        }
    } // i
}

// ---------------- launch ----------------
extern "C" void kernel_launch(void* const* d_in, const int* in_sizes, int n_in,
                              void* d_out, int out_size) {
    (void)in_sizes; (void)n_in; (void)out_size;
    const float* X  = (const float*)d_in[0];
    const float* U  = (const float*)d_in[1];
    const int*   G  = (const int*)  d_in[2];
    const float* W1 = (const float*)d_in[3];
    const float* b1 = (const float*)d_in[4];
    const float* W2 = (const float*)d_in[5];
    const float* b2 = (const float*)d_in[6];
    const float* W3 = (const float*)d_in[7];
    const float* b3 = (const float*)d_in[8];
    float* out = (float*)d_out;

    sen_prep_meta<<<1, NVAR>>>(G);
    sen_prep_w1h<<<(NVAR * 4 * KTMAX * 1024 + 255) / 256, 256>>>(W1);
    sen_prep_w2h<<<(NCHUNK * W2H + 255) / 256, 256>>>(W2);
    sen_prep_ut<<<(NVAR * BATCH + 255) / 256, 256>>>(U);

    cudaFuncSetAttribute(sen_main, cudaFuncAttributeMaxDynamicSharedMemorySize, SMEM_TOTAL);
    sen_main<<<NCTA, 256, SMEM_TOTAL>>>(X, b1, b2, W3, b3, out);
}